// round 8
// baseline (speedup 1.0000x reference)
#include <cuda_runtime.h>
#include <cuda_bf16.h>
#include <math.h>
#include <stdint.h>

#define NBATCH 2
#define SEQ 2048
#define EMBD 1024
#define NHEAD 16
#define HDIM 64
#define ATT_SCALE 0.03125f
#define SKW 72                    // bf16 smem row stride: 16B-aligned, ldmatrix conflict-free

// scratch
__device__ float g_v[(size_t)NBATCH * NHEAD * SEQ * HDIM];            // fp32 V (colsum source)
__device__ float g_sv4[(size_t)NBATCH * NHEAD * 4 * HDIM];            // partial masked colsums
__device__ float g_mcnt[(size_t)NBATCH * NHEAD * 4];                  // partial mask counts
__device__ __nv_bfloat16 g_mbf[(size_t)NBATCH * SEQ];                 // mask as bf16
__device__ __nv_bfloat16 g_qbf[(size_t)NBATCH * NHEAD * SEQ * HDIM];  // pre-scaled by 1/32
__device__ __nv_bfloat16 g_kbf[(size_t)NBATCH * NHEAD * SEQ * HDIM];
__device__ __nv_bfloat16 g_vbf[(size_t)NBATCH * NHEAD * SEQ * HDIM];
__device__ __nv_bfloat16 g_ahi[(size_t)NBATCH * SEQ * EMBD];
__device__ __nv_bfloat16 g_alo[(size_t)NBATCH * SEQ * EMBD];
__device__ __nv_bfloat16 g_whi[(size_t)EMBD * EMBD];
__device__ __nv_bfloat16 g_wlo[(size_t)EMBD * EMBD];

// ===================== helpers =====================
__device__ __forceinline__ uint32_t smem_u32(const void* p) {
    uint32_t a;
    asm("{ .reg .u64 t; cvta.to.shared.u64 t, %1; cvt.u32.u64 %0, t; }" : "=r"(a) : "l"(p));
    return a;
}
__device__ __forceinline__ void cp16(uint32_t s, const void* g) {
    asm volatile("cp.async.ca.shared.global [%0], [%1], 16;" :: "r"(s), "l"(g));
}
#define CP_COMMIT() asm volatile("cp.async.commit_group;" ::: "memory")
#define CP_WAIT(n)  asm volatile("cp.async.wait_group %0;" :: "n"(n) : "memory")

__device__ __forceinline__ void mma_bf16(float* c, uint32_t a0, uint32_t a1, uint32_t a2, uint32_t a3,
                                         uint32_t b0, uint32_t b1) {
    asm volatile("mma.sync.aligned.m16n8k16.row.col.f32.bf16.bf16.f32 "
                 "{%0,%1,%2,%3}, {%4,%5,%6,%7}, {%8,%9}, {%0,%1,%2,%3};"
                 : "+f"(c[0]), "+f"(c[1]), "+f"(c[2]), "+f"(c[3])
                 : "r"(a0), "r"(a1), "r"(a2), "r"(a3), "r"(b0), "r"(b1));
}
__device__ __forceinline__ void ldm4(uint32_t& r0, uint32_t& r1, uint32_t& r2, uint32_t& r3, uint32_t a) {
    asm volatile("ldmatrix.sync.aligned.m8n8.x4.shared.b16 {%0,%1,%2,%3}, [%4];"
                 : "=r"(r0), "=r"(r1), "=r"(r2), "=r"(r3) : "r"(a));
}
__device__ __forceinline__ void ldm4t(uint32_t& r0, uint32_t& r1, uint32_t& r2, uint32_t& r3, uint32_t a) {
    asm volatile("ldmatrix.sync.aligned.m8n8.x4.trans.shared.b16 {%0,%1,%2,%3}, [%4];"
                 : "=r"(r0), "=r"(r1), "=r"(r2), "=r"(r3) : "r"(a));
}
__device__ __forceinline__ uint32_t f2bf2(float lo, float hi) {
    uint32_t u;
    asm("cvt.rn.bf16x2.f32 %0, %1, %2;" : "=r"(u) : "f"(hi), "f"(lo));
    return u;
}

// ---------------------------------------------------------------------------
// Kernel 1: projections via HMMA (3-way bf16 split). 128 rows x one head/block.
// ---------------------------------------------------------------------------
#define P_XH 0
#define P_XL 18432
#define P_WH 36864
#define P_WL 46080
#define P_TOTAL 55296

__device__ __forceinline__ void proj_load_x(char* smc, const float* __restrict__ x, int t) {
    for (int i = t; i < 2048; i += 256) {
        int r = i >> 4, c4 = (i & 15) * 4;
        float4 v = *(const float4*)(x + (size_t)r * EMBD + c4);
        uint32_t h01 = f2bf2(v.x, v.y), h23 = f2bf2(v.z, v.w);
        float r0 = v.x - __uint_as_float(h01 << 16);
        float r1 = v.y - __uint_as_float(h01 & 0xffff0000u);
        float r2 = v.z - __uint_as_float(h23 << 16);
        float r3 = v.w - __uint_as_float(h23 & 0xffff0000u);
        uint32_t so = (uint32_t)((r * SKW + c4) * 2);
        *(uint2*)(smc + P_XH + so) = make_uint2(h01, h23);
        *(uint2*)(smc + P_XL + so) = make_uint2(f2bf2(r0, r1), f2bf2(r2, r3));
    }
}
__device__ __forceinline__ void proj_load_w(char* smc, const float* __restrict__ W, int t) {
    for (int i = t; i < 1024; i += 256) {
        int r = i >> 4, c4 = (i & 15) * 4;
        float4 v = *(const float4*)(W + r * 64 + c4);
        uint32_t h01 = f2bf2(v.x, v.y), h23 = f2bf2(v.z, v.w);
        float r0 = v.x - __uint_as_float(h01 << 16);
        float r1 = v.y - __uint_as_float(h01 & 0xffff0000u);
        float r2 = v.z - __uint_as_float(h23 << 16);
        float r3 = v.w - __uint_as_float(h23 & 0xffff0000u);
        uint32_t so = (uint32_t)((r * SKW + c4) * 2);
        *(uint2*)(smc + P_WH + so) = make_uint2(h01, h23);
        *(uint2*)(smc + P_WL + so) = make_uint2(f2bf2(r0, r1), f2bf2(r2, r3));
    }
}
__device__ __forceinline__ void proj_mm(uint32_t sb, int wr, int lane, float (&c)[8][4]) {
    const uint32_t arow = (uint32_t)(wr + (lane & 7) + ((lane & 8) ? 8 : 0));
    const uint32_t acs = (lane & 16) ? 8u : 0u;
    const uint32_t brow = (uint32_t)(((lane & 16) ? 8 : 0) + (lane & 7));
    const uint32_t bcs = (lane & 8) ? 8u : 0u;
    #pragma unroll
    for (int kk = 0; kk < 4; kk++) {
        uint32_t xh[4], xl[4];
        ldm4(xh[0], xh[1], xh[2], xh[3], sb + P_XH + (arow * SKW + kk * 16 + acs) * 2);
        ldm4(xl[0], xl[1], xl[2], xl[3], sb + P_XL + (arow * SKW + kk * 16 + acs) * 2);
        #pragma unroll
        for (int p = 0; p < 4; p++) {
            uint32_t off = ((p * 16 + brow) * SKW + kk * 16 + bcs) * 2;
            uint32_t bh0, bh1, bh2, bh3, bl0, bl1, bl2, bl3;
            ldm4(bh0, bh1, bh2, bh3, sb + P_WH + off);
            ldm4(bl0, bl1, bl2, bl3, sb + P_WL + off);
            mma_bf16(c[2 * p],     xh[0], xh[1], xh[2], xh[3], bh0, bh1);
            mma_bf16(c[2 * p],     xh[0], xh[1], xh[2], xh[3], bl0, bl1);
            mma_bf16(c[2 * p],     xl[0], xl[1], xl[2], xl[3], bh0, bh1);
            mma_bf16(c[2 * p + 1], xh[0], xh[1], xh[2], xh[3], bh2, bh3);
            mma_bf16(c[2 * p + 1], xh[0], xh[1], xh[2], xh[3], bl2, bl3);
            mma_bf16(c[2 * p + 1], xl[0], xl[1], xl[2], xl[3], bh2, bh3);
        }
    }
}
__device__ __forceinline__ void proj_mm_regA(uint32_t sb, int lane,
                                             const uint32_t (&ah)[4][4], const uint32_t (&al)[4][4],
                                             float (&c)[8][4]) {
    const uint32_t brow = (uint32_t)(((lane & 16) ? 8 : 0) + (lane & 7));
    const uint32_t bcs = (lane & 8) ? 8u : 0u;
    #pragma unroll
    for (int kk = 0; kk < 4; kk++) {
        #pragma unroll
        for (int p = 0; p < 4; p++) {
            uint32_t off = ((p * 16 + brow) * SKW + kk * 16 + bcs) * 2;
            uint32_t bh0, bh1, bh2, bh3, bl0, bl1, bl2, bl3;
            ldm4(bh0, bh1, bh2, bh3, sb + P_WH + off);
            ldm4(bl0, bl1, bl2, bl3, sb + P_WL + off);
            mma_bf16(c[2 * p],     ah[kk][0], ah[kk][1], ah[kk][2], ah[kk][3], bh0, bh1);
            mma_bf16(c[2 * p],     ah[kk][0], ah[kk][1], ah[kk][2], ah[kk][3], bl0, bl1);
            mma_bf16(c[2 * p],     al[kk][0], al[kk][1], al[kk][2], al[kk][3], bh0, bh1);
            mma_bf16(c[2 * p + 1], ah[kk][0], ah[kk][1], ah[kk][2], ah[kk][3], bh2, bh3);
            mma_bf16(c[2 * p + 1], ah[kk][0], ah[kk][1], ah[kk][2], ah[kk][3], bl2, bl3);
            mma_bf16(c[2 * p + 1], al[kk][0], al[kk][1], al[kk][2], al[kk][3], bh2, bh3);
        }
    }
}

__global__ __launch_bounds__(256, 2) void proj_hmma(
    const float* __restrict__ keys, const float* __restrict__ queries,
    const float* __restrict__ Wk, const float* __restrict__ Wq, const float* __restrict__ Wv)
{
    extern __shared__ char smc[];
    const uint32_t sb = smem_u32(smc);
    const int t = threadIdx.x, w = t >> 5, lane = t & 31;
    const int grow = lane >> 2, qr = lane & 3;
    const int wr = w * 16;
    const int n = blockIdx.z, h = blockIdx.y, l0 = blockIdx.x * 128;
    const size_t hb = ((size_t)(n * NHEAD + h) * SEQ + l0) * HDIM;
    const float* xq = queries + ((size_t)n * SEQ + l0) * EMBD + h * HDIM;
    const float* xk = keys    + ((size_t)n * SEQ + l0) * EMBD + h * HDIM;

    // ---- q ----
    proj_load_x(smc, xq, t);
    proj_load_w(smc, Wq, t);
    __syncthreads();
    float c[8][4];
    #pragma unroll
    for (int i = 0; i < 8; i++)
        #pragma unroll
        for (int j = 0; j < 4; j++) c[i][j] = 0.0f;
    proj_mm(sb, wr, lane, c);
    __syncthreads();

    uint32_t qh[4][4], ql[4][4];
    #pragma unroll
    for (int nt = 0; nt < 8; nt++) {
        uint32_t h0 = f2bf2(c[nt][0], c[nt][1]);
        uint32_t h1 = f2bf2(c[nt][2], c[nt][3]);
        float r0 = c[nt][0] - __uint_as_float(h0 << 16);
        float r1 = c[nt][1] - __uint_as_float(h0 & 0xffff0000u);
        float r2 = c[nt][2] - __uint_as_float(h1 << 16);
        float r3 = c[nt][3] - __uint_as_float(h1 & 0xffff0000u);
        qh[nt >> 1][(nt & 1) * 2 + 0] = h0;
        qh[nt >> 1][(nt & 1) * 2 + 1] = h1;
        ql[nt >> 1][(nt & 1) * 2 + 0] = f2bf2(r0, r1);
        ql[nt >> 1][(nt & 1) * 2 + 1] = f2bf2(r2, r3);
        int col = nt * 8 + qr * 2;
        *(uint32_t*)(g_qbf + hb + (size_t)(wr + grow) * HDIM + col) =
            f2bf2(c[nt][0] * ATT_SCALE, c[nt][1] * ATT_SCALE);
        *(uint32_t*)(g_qbf + hb + (size_t)(wr + grow + 8) * HDIM + col) =
            f2bf2(c[nt][2] * ATT_SCALE, c[nt][3] * ATT_SCALE);
    }

    // ---- k ----
    proj_load_x(smc, xk, t);
    proj_load_w(smc, Wk, t);
    __syncthreads();
    #pragma unroll
    for (int i = 0; i < 8; i++)
        #pragma unroll
        for (int j = 0; j < 4; j++) c[i][j] = 0.0f;
    proj_mm(sb, wr, lane, c);
    __syncthreads();
    #pragma unroll
    for (int nt = 0; nt < 8; nt++) {
        int col = nt * 8 + qr * 2;
        *(uint32_t*)(g_kbf + hb + (size_t)(wr + grow) * HDIM + col) = f2bf2(c[nt][0], c[nt][1]);
        *(uint32_t*)(g_kbf + hb + (size_t)(wr + grow + 8) * HDIM + col) = f2bf2(c[nt][2], c[nt][3]);
    }

    // ---- v = q Wv^T ----
    proj_load_w(smc, Wv, t);
    __syncthreads();
    #pragma unroll
    for (int i = 0; i < 8; i++)
        #pragma unroll
        for (int j = 0; j < 4; j++) c[i][j] = 0.0f;
    proj_mm_regA(sb, lane, qh, ql, c);
    #pragma unroll
    for (int nt = 0; nt < 8; nt++) {
        int col = nt * 8 + qr * 2;
        *(uint32_t*)(g_vbf + hb + (size_t)(wr + grow) * HDIM + col) = f2bf2(c[nt][0], c[nt][1]);
        *(uint32_t*)(g_vbf + hb + (size_t)(wr + grow + 8) * HDIM + col) = f2bf2(c[nt][2], c[nt][3]);
        *(float2*)(g_v + hb + (size_t)(wr + grow) * HDIM + col) = make_float2(c[nt][0], c[nt][1]);
        *(float2*)(g_v + hb + (size_t)(wr + grow + 8) * HDIM + col) = make_float2(c[nt][2], c[nt][3]);
    }
}

// ---------------------------------------------------------------------------
// Kernel 1b: masked V column sums + mask counts + bf16 mask (fused)
// ---------------------------------------------------------------------------
__global__ __launch_bounds__(256) void colsum_kernel(const int* __restrict__ mask)
{
    const int bid = blockIdx.x, y = blockIdx.y;
    const float* V = g_v + (size_t)bid * SEQ * HDIM + (size_t)y * 512 * HDIM;
    const int* mg = mask + (bid >> 4) * SEQ + y * 512;
    const int d = threadIdx.x & 63, grp = threadIdx.x >> 6;
    float s = 0.0f;
    int scnt = 0;
    const float* vp = V + (size_t)grp * 128 * HDIM + d;
    const int* mp = mg + grp * 128;
    #pragma unroll 8
    for (int cc = 0; cc < 128; cc++) {
        int m = mp[cc];
        s = fmaf((float)m, vp[(size_t)cc * HDIM], s);
        scnt += m;
    }
    // fused mask_prep (only 1 head block per (n, y) writes)
    if ((bid & 15) == 0)
        for (int j = threadIdx.x; j < 512; j += 256)
            g_mbf[(bid >> 4) * SEQ + y * 512 + j] = __float2bfloat16((float)mg[j]);
    __shared__ float red[256];
    __shared__ int redc[4];
    red[threadIdx.x] = s;
    if (d == 0) redc[grp] = scnt;
    __syncthreads();
    if (threadIdx.x < 64)
        g_sv4[((size_t)bid * 4 + y) * HDIM + threadIdx.x] =
            red[threadIdx.x] + red[64 + threadIdx.x] + red[128 + threadIdx.x] + red[192 + threadIdx.x];
    if (threadIdx.x == 0)
        g_mcnt[bid * 4 + y] = (float)(redc[0] + redc[1] + redc[2] + redc[3]);
}

// ---------------------------------------------------------------------------
// Kernel 2: HMMA flash attention (unchanged from R7)
// ---------------------------------------------------------------------------
#define A_QS 0
#define A_KS0 18432
#define A_KS1 36864
#define A_VS0 55296
#define A_VS1 73728
#define A_MSK0 92160
#define A_MSK1 92416
#define A_SVR 92672
#define A_CNT 92928
#define A_TOTAL 92944

__global__ __launch_bounds__(256, 2) void attn_hmma()
{
    extern __shared__ char smc[];
    const uint32_t sb = smem_u32(smc);
    const int t = threadIdx.x;
    const int w = t >> 5, lane = t & 31;
    const int grow = lane >> 2, qr = lane & 3;
    const int wr = w * 16;
    const int n = blockIdx.z, h = blockIdx.y, q0 = blockIdx.x * 128;
    const size_t hb = (size_t)(n * NHEAD + h) * SEQ;
    const __nv_bfloat16* Qg = g_qbf + (hb + q0) * HDIM;
    const __nv_bfloat16* Kg = g_kbf + hb * HDIM;
    const __nv_bfloat16* Vg = g_vbf + hb * HDIM;
    const __nv_bfloat16* Mg = g_mbf + n * SEQ;

    for (int i = t; i < 1024; i += 256) {
        int r = i >> 3, ch = i & 7;
        uint32_t so = (uint32_t)((r * SKW + ch * 8) * 2);
        cp16(sb + A_QS + so, Qg + r * 64 + ch * 8);
        cp16(sb + A_KS0 + so, Kg + r * 64 + ch * 8);
        cp16(sb + A_VS0 + so, Vg + r * 64 + ch * 8);
    }
    if (t < 16) cp16(sb + A_MSK0 + t * 16, Mg + t * 8);
    if (t < 64) {
        const float* s4 = g_sv4 + (size_t)(n * NHEAD + h) * 4 * HDIM;
        ((float*)(smc + A_SVR))[t] = s4[t] + s4[64 + t] + s4[128 + t] + s4[192 + t];
    }
    if (t < 4) ((float*)(smc + A_CNT))[t] = g_mcnt[(n * NHEAD + h) * 4 + t];
    CP_COMMIT();
    CP_WAIT(0);
    __syncthreads();

    uint32_t qf[4][4];
    {
        uint32_t qrow = (uint32_t)(wr + (lane & 7) + ((lane & 8) ? 8 : 0));
        uint32_t qcs = (lane & 16) ? 8u : 0u;
        #pragma unroll
        for (int kk = 0; kk < 4; kk++)
            ldm4(qf[kk][0], qf[kk][1], qf[kk][2], qf[kk][3],
                 sb + A_QS + (qrow * SKW + kk * 16 + qcs) * 2);
    }

    float of[9][4];
    #pragma unroll
    for (int i = 0; i < 9; i++)
        #pragma unroll
        for (int j = 0; j < 4; j++) of[i][j] = 0.0f;

    const uint32_t krow_b = (uint32_t)(lane & 7);
    const uint32_t ke = ((uint32_t)(lane >> 3)) * 8;
    const uint32_t vrow_b = (uint32_t)(((lane & 8) ? 8 : 0) + (lane & 7));
    const uint32_t vcs = (lane & 16) ? 8u : 0u;
    const uint32_t bones = (lane < 4) ? 0x3F803F80u : 0u;

    const __nv_bfloat162 C24 = __float2bfloat162_rn(4.1666667e-2f);
    const __nv_bfloat162 C6  = __float2bfloat162_rn(1.6666667e-1f);
    const __nv_bfloat162 C2  = __float2bfloat162_rn(0.5f);
    const __nv_bfloat162 C1  = __float2bfloat162_rn(1.0f);

    for (int tile = 0; tile < 16; tile++) {
        if (tile) __syncthreads();

        if (tile < 15) {
            const int kn = tile * 128 + 128;
            const __nv_bfloat16* ks = Kg + (size_t)kn * HDIM;
            const __nv_bfloat16* vs = Vg + (size_t)kn * HDIM;
            uint32_t kb = sb + ((tile + 1) & 1 ? A_KS1 : A_KS0);
            uint32_t vb = sb + ((tile + 1) & 1 ? A_VS1 : A_VS0);
            for (int i = t; i < 1024; i += 256) {
                int r = i >> 3, ch = i & 7;
                uint32_t so = (uint32_t)((r * SKW + ch * 8) * 2);
                cp16(kb + so, ks + r * 64 + ch * 8);
                cp16(vb + so, vs + r * 64 + ch * 8);
            }
            if (t < 16) cp16(sb + ((tile + 1) & 1 ? A_MSK1 : A_MSK0) + t * 16, Mg + kn + t * 8);
            CP_COMMIT();
            CP_WAIT(1);
        } else {
            CP_WAIT(0);
        }
        __syncthreads();

        const uint32_t kb = sb + (tile & 1 ? A_KS1 : A_KS0);
        const uint32_t vb = sb + (tile & 1 ? A_VS1 : A_VS0);
        const char* mskb = smc + (tile & 1 ? A_MSK1 : A_MSK0);

        uint32_t pf[8][4];
        #pragma unroll
        for (int ct = 0; ct < 16; ct++) {
            float sa[4] = {0.0f, 0.0f, 0.0f, 0.0f};
            uint32_t base = kb + ((ct * 8 + krow_b) * SKW + ke) * 2;
            uint32_t b0, b1, b2, b3, b4, b5, b6, b7;
            ldm4(b0, b1, b2, b3, base);
            ldm4(b4, b5, b6, b7, base + 64);
            mma_bf16(sa, qf[0][0], qf[0][1], qf[0][2], qf[0][3], b0, b1);
            mma_bf16(sa, qf[1][0], qf[1][1], qf[1][2], qf[1][3], b2, b3);
            mma_bf16(sa, qf[2][0], qf[2][1], qf[2][2], qf[2][3], b4, b5);
            mma_bf16(sa, qf[3][0], qf[3][1], qf[3][2], qf[3][3], b6, b7);

            __nv_bfloat162 m2 = *(const __nv_bfloat162*)(mskb + ct * 16 + qr * 4);
            __nv_bfloat162 x01, x23;
            *(uint32_t*)&x01 = f2bf2(sa[0], sa[1]);
            *(uint32_t*)&x23 = f2bf2(sa[2], sa[3]);
            __nv_bfloat162 q01 = __hfma2(x01, __hfma2(x01, __hfma2(x01, C24, C6), C2), C1);
            __nv_bfloat162 q23 = __hfma2(x23, __hfma2(x23, __hfma2(x23, C24, C6), C2), C1);
            __nv_bfloat162 d01 = __hmul2(__hmul2(x01, q01), m2);
            __nv_bfloat162 d23 = __hmul2(__hmul2(x23, q23), m2);
            pf[ct >> 1][(ct & 1) * 2 + 0] = *(uint32_t*)&d01;
            pf[ct >> 1][(ct & 1) * 2 + 1] = *(uint32_t*)&d23;
        }

        #pragma unroll
        for (int kk = 0; kk < 8; kk++) {
            uint32_t rbase = vb + ((kk * 16 + vrow_b) * SKW + vcs) * 2;
            #pragma unroll
            for (int dg = 0; dg < 4; dg++) {
                uint32_t v0, v1, v2, v3;
                ldm4t(v0, v1, v2, v3, rbase + dg * 32);
                mma_bf16(of[2 * dg],     pf[kk][0], pf[kk][1], pf[kk][2], pf[kk][3], v0, v1);
                mma_bf16(of[2 * dg + 1], pf[kk][0], pf[kk][1], pf[kk][2], pf[kk][3], v2, v3);
            }
            mma_bf16(of[8], pf[kk][0], pf[kk][1], pf[kk][2], pf[kk][3], bones, bones);
        }
    }

    const float* c4 = (const float*)(smc + A_CNT);
    const float cnt = c4[0] + c4[1] + c4[2] + c4[3];
    float sd0 = __shfl_sync(0xffffffffu, of[8][0], lane & 28);
    float sd1 = __shfl_sync(0xffffffffu, of[8][2], lane & 28);
    const float inv0 = 1.0f / (cnt + sd0), inv1 = 1.0f / (cnt + sd1);

    const float* sv = (const float*)(smc + A_SVR);
    const size_t base0 = ((size_t)n * SEQ + q0 + wr + grow) * EMBD + h * HDIM;
    const size_t base1 = base0 + (size_t)8 * EMBD;
    #pragma unroll
    for (int dt = 0; dt < 8; dt++) {
        int j0 = dt * 8 + qr * 2;
        float o00 = (of[dt][0] + sv[j0]) * inv0;
        float o01 = (of[dt][1] + sv[j0 + 1]) * inv0;
        float o10 = (of[dt][2] + sv[j0]) * inv1;
        float o11 = (of[dt][3] + sv[j0 + 1]) * inv1;
        uint32_t h0 = f2bf2(o00, o01);
        uint32_t h1 = f2bf2(o10, o11);
        float r00 = o00 - __uint_as_float(h0 << 16);
        float r01 = o01 - __uint_as_float(h0 & 0xffff0000u);
        float r10 = o10 - __uint_as_float(h1 << 16);
        float r11 = o11 - __uint_as_float(h1 & 0xffff0000u);
        *(uint32_t*)(g_ahi + base0 + j0) = h0;
        *(uint32_t*)(g_ahi + base1 + j0) = h1;
        *(uint32_t*)(g_alo + base0 + j0) = f2bf2(r00, r01);
        *(uint32_t*)(g_alo + base1 + j0) = f2bf2(r10, r11);
    }
}

// ---------------------------------------------------------------------------
// Kernel 3a: Wo -> hi/lo bf16 split
// ---------------------------------------------------------------------------
__global__ __launch_bounds__(256) void wo_prep(const float* __restrict__ Wo)
{
    int i = blockIdx.x * 256 + threadIdx.x;
    float wv = Wo[i];
    __nv_bfloat16 hi = __float2bfloat16(wv);
    g_whi[i] = hi;
    g_wlo[i] = __float2bfloat16(wv - __bfloat162float(hi));
}

// ---------------------------------------------------------------------------
// Kernel 3b: out = attn @ Wo^T + bo. 3-stage k=32 cp.async pipeline,
// XOR-swizzled zero-pad smem (32KB/stage) -> 2 CTAs/SM -> 1 wave.
// Swizzle: 16B-chunk ch -> ch ^ ((row>>1)&3) on 64B row stride.
// ---------------------------------------------------------------------------
#define OB_AH 0
#define OB_AL 8192
#define OB_WH 16384
#define OB_WL 24576
#define O_STG 32768
#define O_TOTAL (3 * O_STG)

__device__ __forceinline__ void o_load_stage(
    uint32_t dst, const __nv_bfloat16* __restrict__ AH, const __nv_bfloat16* __restrict__ AL,
    const __nv_bfloat16* __restrict__ WH, const __nv_bfloat16* __restrict__ WL,
    int t, size_t gb)
{
    #pragma unroll
    for (int i = t; i < 512; i += 256) {
        int r = i >> 2, ch = i & 3;
        uint32_t so = (uint32_t)(r * 64 + ((ch ^ ((r >> 1) & 3)) << 4));
        size_t go = (size_t)r * EMBD + gb + ch * 8;
        cp16(dst + OB_AH + so, AH + go);
        cp16(dst + OB_AL + so, AL + go);
        cp16(dst + OB_WH + so, WH + go);
        cp16(dst + OB_WL + so, WL + go);
    }
}
__device__ __forceinline__ uint32_t o_sw(uint32_t row, uint32_t c16) {
    return row * 64 + ((c16 ^ ((row >> 1) & 3)) << 4);
}

__global__ __launch_bounds__(256, 2) void out_hmma(const float* __restrict__ bo, float* __restrict__ out)
{
    extern __shared__ char smc[];
    const uint32_t sb = smem_u32(smc);
    const int t = threadIdx.x;
    const int w = t >> 5, lane = t & 31;
    const int grow = lane >> 2, qr = lane & 3;
    const int o0 = blockIdx.x * 128, m0 = blockIdx.y * 128;
    const int my = (w >> 2) * 64, ox = (w & 3) * 32;

    const __nv_bfloat16* AHg = g_ahi + (size_t)m0 * EMBD;
    const __nv_bfloat16* ALg = g_alo + (size_t)m0 * EMBD;
    const __nv_bfloat16* WHg = g_whi + (size_t)o0 * EMBD;
    const __nv_bfloat16* WLg = g_wlo + (size_t)o0 * EMBD;

    o_load_stage(sb, AHg, ALg, WHg, WLg, t, 0);
    CP_COMMIT();
    o_load_stage(sb + O_STG, AHg, ALg, WHg, WLg, t, 32);
    CP_COMMIT();

    float cf[4][4][4];
    #pragma unroll
    for (int i = 0; i < 4; i++)
        #pragma unroll
        for (int j = 0; j < 4; j++)
            #pragma unroll
            for (int k = 0; k < 4; k++) cf[i][j][k] = 0.0f;

    const uint32_t arow = (uint32_t)(my + (lane & 7) + ((lane & 8) ? 8 : 0));
    const uint32_t ac16 = (lane & 16) ? 1u : 0u;
    const uint32_t brow = (uint32_t)(ox + ((lane & 16) ? 8 : 0) + (lane & 7));
    const uint32_t bc16 = (lane & 8) ? 1u : 0u;

    int stage = 0;
    for (int ec = 0; ec < 32; ec++) {
        if (ec < 30) { CP_WAIT(1); } else { CP_WAIT(0); }
        __syncthreads();
        if (ec < 30) {
            int ns = stage + 2; if (ns >= 3) ns -= 3;
            o_load_stage(sb + ns * O_STG, AHg, ALg, WHg, WLg, t, (size_t)(ec + 2) * 32);
            CP_COMMIT();
        }

        const uint32_t st = sb + stage * O_STG;
        #pragma unroll
        for (int kk = 0; kk < 2; kk++) {
            uint32_t ah[4][4], al[4][4], bh[4][2], bl[4][2];
            #pragma unroll
            for (int mt = 0; mt < 4; mt++) {
                uint32_t off = o_sw(arow + mt * 16, kk * 2 + ac16);
                ldm4(ah[mt][0], ah[mt][1], ah[mt][2], ah[mt][3], st + OB_AH + off);
                ldm4(al[mt][0], al[mt][1], al[mt][2], al[mt][3], st + OB_AL + off);
            }
            #pragma unroll
            for (int p = 0; p < 2; p++) {
                uint32_t off = o_sw(brow + p * 16, kk * 2 + bc16);
                ldm4(bh[2 * p][0], bh[2 * p][1], bh[2 * p + 1][0], bh[2 * p + 1][1], st + OB_WH + off);
                ldm4(bl[2 * p][0], bl[2 * p][1], bl[2 * p + 1][0], bl[2 * p + 1][1], st + OB_WL + off);
            }
            #pragma unroll
            for (int mt = 0; mt < 4; mt++)
                #pragma unroll
                for (int nt = 0; nt < 4; nt++) {
                    mma_bf16(cf[mt][nt], ah[mt][0], ah[mt][1], ah[mt][2], ah[mt][3], bh[nt][0], bh[nt][1]);
                    mma_bf16(cf[mt][nt], ah[mt][0], ah[mt][1], ah[mt][2], ah[mt][3], bl[nt][0], bl[nt][1]);
                    mma_bf16(cf[mt][nt], al[mt][0], al[mt][1], al[mt][2], al[mt][3], bh[nt][0], bh[nt][1]);
                }
        }
        if (++stage == 3) stage = 0;
    }

    #pragma unroll
    for (int mt = 0; mt < 4; mt++) {
        int row = m0 + my + mt * 16 + grow;
        #pragma unroll
        for (int nt = 0; nt < 4; nt++) {
            int col = o0 + ox + nt * 8 + qr * 2;
            float b0 = bo[col], b1 = bo[col + 1];
            *(float2*)(out + (size_t)row * EMBD + col) =
                make_float2(cf[mt][nt][0] + b0, cf[mt][nt][1] + b1);
            *(float2*)(out + (size_t)(row + 8) * EMBD + col) =
                make_float2(cf[mt][nt][2] + b0, cf[mt][nt][3] + b1);
        }
    }
}

// ---------------------------------------------------------------------------
extern "C" void kernel_launch(void* const* d_in, const int* in_sizes, int n_in,
                              void* d_out, int out_size)
{
    const float* keys    = (const float*)d_in[0];
    const float* queries = (const float*)d_in[1];
    const int*   mask    = (const int*)d_in[3];
    const float* Wk      = (const float*)d_in[4];
    const float* Wq      = (const float*)d_in[5];
    const float* Wv      = (const float*)d_in[6];
    const float* Wo      = (const float*)d_in[7];
    const float* bo      = (const float*)d_in[8];
    float* out = (float*)d_out;

    cudaFuncSetAttribute(proj_hmma, cudaFuncAttributeMaxDynamicSharedMemorySize, P_TOTAL);
    cudaFuncSetAttribute(attn_hmma, cudaFuncAttributeMaxDynamicSharedMemorySize, A_TOTAL);
    cudaFuncSetAttribute(out_hmma, cudaFuncAttributeMaxDynamicSharedMemorySize, O_TOTAL);

    dim3 gp(SEQ / 128, NHEAD, NBATCH);
    proj_hmma<<<gp, 256, P_TOTAL>>>(keys, queries, Wk, Wq, Wv);
    dim3 gc(NBATCH * NHEAD, 4);
    colsum_kernel<<<gc, 256>>>(mask);
    wo_prep<<<(EMBD * EMBD) / 256, 256>>>(Wo);
    dim3 ga(SEQ / 128, NHEAD, NBATCH);
    attn_hmma<<<ga, 256, A_TOTAL>>>();
    dim3 go(EMBD / 128, NBATCH * SEQ / 128);
    out_hmma<<<go, 256, O_TOTAL>>>(bo, out);
}

// round 9
// speedup vs baseline: 1.0592x; 1.0592x over previous
#include <cuda_runtime.h>
#include <cuda_bf16.h>
#include <math.h>
#include <stdint.h>

#define NBATCH 2
#define SEQ 2048
#define EMBD 1024
#define NHEAD 16
#define HDIM 64
#define ATT_SCALE 0.03125f
#define SKW 72                    // bf16 smem row stride: 16B-aligned, ldmatrix conflict-free

// scratch
__device__ float g_v[(size_t)NBATCH * NHEAD * SEQ * HDIM];            // fp32 V (colsum source)
__device__ float g_sv4[(size_t)NBATCH * NHEAD * 4 * HDIM];            // partial masked colsums
__device__ float g_mcnt[(size_t)NBATCH * NHEAD * 4];                  // partial mask counts
__device__ __nv_bfloat16 g_qbf[(size_t)NBATCH * NHEAD * SEQ * HDIM];  // pre-scaled by 1/32
__device__ __nv_bfloat16 g_kbf[(size_t)NBATCH * NHEAD * SEQ * HDIM];  // pre-masked (k * mask)
__device__ __nv_bfloat16 g_vbf[(size_t)NBATCH * NHEAD * SEQ * HDIM];
__device__ __nv_bfloat16 g_ahi[(size_t)NBATCH * SEQ * EMBD];
__device__ __nv_bfloat16 g_alo[(size_t)NBATCH * SEQ * EMBD];
__device__ __nv_bfloat16 g_whi[(size_t)EMBD * EMBD];
__device__ __nv_bfloat16 g_wlo[(size_t)EMBD * EMBD];

// ===================== helpers =====================
__device__ __forceinline__ uint32_t smem_u32(const void* p) {
    uint32_t a;
    asm("{ .reg .u64 t; cvta.to.shared.u64 t, %1; cvt.u32.u64 %0, t; }" : "=r"(a) : "l"(p));
    return a;
}
__device__ __forceinline__ void cp16(uint32_t s, const void* g) {
    asm volatile("cp.async.ca.shared.global [%0], [%1], 16;" :: "r"(s), "l"(g));
}
#define CP_COMMIT() asm volatile("cp.async.commit_group;" ::: "memory")
#define CP_WAIT(n)  asm volatile("cp.async.wait_group %0;" :: "n"(n) : "memory")

__device__ __forceinline__ void mma_bf16(float* c, uint32_t a0, uint32_t a1, uint32_t a2, uint32_t a3,
                                         uint32_t b0, uint32_t b1) {
    asm volatile("mma.sync.aligned.m16n8k16.row.col.f32.bf16.bf16.f32 "
                 "{%0,%1,%2,%3}, {%4,%5,%6,%7}, {%8,%9}, {%0,%1,%2,%3};"
                 : "+f"(c[0]), "+f"(c[1]), "+f"(c[2]), "+f"(c[3])
                 : "r"(a0), "r"(a1), "r"(a2), "r"(a3), "r"(b0), "r"(b1));
}
__device__ __forceinline__ void ldm4(uint32_t& r0, uint32_t& r1, uint32_t& r2, uint32_t& r3, uint32_t a) {
    asm volatile("ldmatrix.sync.aligned.m8n8.x4.shared.b16 {%0,%1,%2,%3}, [%4];"
                 : "=r"(r0), "=r"(r1), "=r"(r2), "=r"(r3) : "r"(a));
}
__device__ __forceinline__ void ldm4t(uint32_t& r0, uint32_t& r1, uint32_t& r2, uint32_t& r3, uint32_t a) {
    asm volatile("ldmatrix.sync.aligned.m8n8.x4.trans.shared.b16 {%0,%1,%2,%3}, [%4];"
                 : "=r"(r0), "=r"(r1), "=r"(r2), "=r"(r3) : "r"(a));
}
__device__ __forceinline__ uint32_t f2bf2(float lo, float hi) {
    uint32_t u;
    asm("cvt.rn.bf16x2.f32 %0, %1, %2;" : "=r"(u) : "f"(hi), "f"(lo));
    return u;
}

// ---------------------------------------------------------------------------
// Kernel 1: projections via HMMA (3-way bf16 split). 128 rows x one head/block.
// k output is pre-multiplied by the attention mask (masked keys -> 0 -> delta 0).
// ---------------------------------------------------------------------------
#define P_XH 0
#define P_XL 18432
#define P_WH 36864
#define P_WL 46080
#define P_TOTAL 55296

__device__ __forceinline__ void proj_load_x(char* smc, const float* __restrict__ x, int t) {
    for (int i = t; i < 2048; i += 256) {
        int r = i >> 4, c4 = (i & 15) * 4;
        float4 v = *(const float4*)(x + (size_t)r * EMBD + c4);
        uint32_t h01 = f2bf2(v.x, v.y), h23 = f2bf2(v.z, v.w);
        float r0 = v.x - __uint_as_float(h01 << 16);
        float r1 = v.y - __uint_as_float(h01 & 0xffff0000u);
        float r2 = v.z - __uint_as_float(h23 << 16);
        float r3 = v.w - __uint_as_float(h23 & 0xffff0000u);
        uint32_t so = (uint32_t)((r * SKW + c4) * 2);
        *(uint2*)(smc + P_XH + so) = make_uint2(h01, h23);
        *(uint2*)(smc + P_XL + so) = make_uint2(f2bf2(r0, r1), f2bf2(r2, r3));
    }
}
__device__ __forceinline__ void proj_load_w(char* smc, const float* __restrict__ W, int t) {
    for (int i = t; i < 1024; i += 256) {
        int r = i >> 4, c4 = (i & 15) * 4;
        float4 v = *(const float4*)(W + r * 64 + c4);
        uint32_t h01 = f2bf2(v.x, v.y), h23 = f2bf2(v.z, v.w);
        float r0 = v.x - __uint_as_float(h01 << 16);
        float r1 = v.y - __uint_as_float(h01 & 0xffff0000u);
        float r2 = v.z - __uint_as_float(h23 << 16);
        float r3 = v.w - __uint_as_float(h23 & 0xffff0000u);
        uint32_t so = (uint32_t)((r * SKW + c4) * 2);
        *(uint2*)(smc + P_WH + so) = make_uint2(h01, h23);
        *(uint2*)(smc + P_WL + so) = make_uint2(f2bf2(r0, r1), f2bf2(r2, r3));
    }
}
__device__ __forceinline__ void proj_mm(uint32_t sb, int wr, int lane, float (&c)[8][4]) {
    const uint32_t arow = (uint32_t)(wr + (lane & 7) + ((lane & 8) ? 8 : 0));
    const uint32_t acs = (lane & 16) ? 8u : 0u;
    const uint32_t brow = (uint32_t)(((lane & 16) ? 8 : 0) + (lane & 7));
    const uint32_t bcs = (lane & 8) ? 8u : 0u;
    #pragma unroll
    for (int kk = 0; kk < 4; kk++) {
        uint32_t xh[4], xl[4];
        ldm4(xh[0], xh[1], xh[2], xh[3], sb + P_XH + (arow * SKW + kk * 16 + acs) * 2);
        ldm4(xl[0], xl[1], xl[2], xl[3], sb + P_XL + (arow * SKW + kk * 16 + acs) * 2);
        #pragma unroll
        for (int p = 0; p < 4; p++) {
            uint32_t off = ((p * 16 + brow) * SKW + kk * 16 + bcs) * 2;
            uint32_t bh0, bh1, bh2, bh3, bl0, bl1, bl2, bl3;
            ldm4(bh0, bh1, bh2, bh3, sb + P_WH + off);
            ldm4(bl0, bl1, bl2, bl3, sb + P_WL + off);
            mma_bf16(c[2 * p],     xh[0], xh[1], xh[2], xh[3], bh0, bh1);
            mma_bf16(c[2 * p],     xh[0], xh[1], xh[2], xh[3], bl0, bl1);
            mma_bf16(c[2 * p],     xl[0], xl[1], xl[2], xl[3], bh0, bh1);
            mma_bf16(c[2 * p + 1], xh[0], xh[1], xh[2], xh[3], bh2, bh3);
            mma_bf16(c[2 * p + 1], xh[0], xh[1], xh[2], xh[3], bl2, bl3);
            mma_bf16(c[2 * p + 1], xl[0], xl[1], xl[2], xl[3], bh2, bh3);
        }
    }
}
__device__ __forceinline__ void proj_mm_regA(uint32_t sb, int lane,
                                             const uint32_t (&ah)[4][4], const uint32_t (&al)[4][4],
                                             float (&c)[8][4]) {
    const uint32_t brow = (uint32_t)(((lane & 16) ? 8 : 0) + (lane & 7));
    const uint32_t bcs = (lane & 8) ? 8u : 0u;
    #pragma unroll
    for (int kk = 0; kk < 4; kk++) {
        #pragma unroll
        for (int p = 0; p < 4; p++) {
            uint32_t off = ((p * 16 + brow) * SKW + kk * 16 + bcs) * 2;
            uint32_t bh0, bh1, bh2, bh3, bl0, bl1, bl2, bl3;
            ldm4(bh0, bh1, bh2, bh3, sb + P_WH + off);
            ldm4(bl0, bl1, bl2, bl3, sb + P_WL + off);
            mma_bf16(c[2 * p],     ah[kk][0], ah[kk][1], ah[kk][2], ah[kk][3], bh0, bh1);
            mma_bf16(c[2 * p],     ah[kk][0], ah[kk][1], ah[kk][2], ah[kk][3], bl0, bl1);
            mma_bf16(c[2 * p],     al[kk][0], al[kk][1], al[kk][2], al[kk][3], bh0, bh1);
            mma_bf16(c[2 * p + 1], ah[kk][0], ah[kk][1], ah[kk][2], ah[kk][3], bh2, bh3);
            mma_bf16(c[2 * p + 1], ah[kk][0], ah[kk][1], ah[kk][2], ah[kk][3], bl2, bl3);
            mma_bf16(c[2 * p + 1], al[kk][0], al[kk][1], al[kk][2], al[kk][3], bh2, bh3);
        }
    }
}

__global__ __launch_bounds__(256, 2) void proj_hmma(
    const float* __restrict__ keys, const float* __restrict__ queries,
    const float* __restrict__ Wk, const float* __restrict__ Wq, const float* __restrict__ Wv,
    const int* __restrict__ mask)
{
    extern __shared__ char smc[];
    const uint32_t sb = smem_u32(smc);
    const int t = threadIdx.x, w = t >> 5, lane = t & 31;
    const int grow = lane >> 2, qr = lane & 3;
    const int wr = w * 16;
    const int n = blockIdx.z, h = blockIdx.y, l0 = blockIdx.x * 128;
    const size_t hb = ((size_t)(n * NHEAD + h) * SEQ + l0) * HDIM;
    const float* xq = queries + ((size_t)n * SEQ + l0) * EMBD + h * HDIM;
    const float* xk = keys    + ((size_t)n * SEQ + l0) * EMBD + h * HDIM;

    // ---- q ----
    proj_load_x(smc, xq, t);
    proj_load_w(smc, Wq, t);
    __syncthreads();
    float c[8][4];
    #pragma unroll
    for (int i = 0; i < 8; i++)
        #pragma unroll
        for (int j = 0; j < 4; j++) c[i][j] = 0.0f;
    proj_mm(sb, wr, lane, c);
    __syncthreads();

    uint32_t qh[4][4], ql[4][4];
    #pragma unroll
    for (int nt = 0; nt < 8; nt++) {
        uint32_t h0 = f2bf2(c[nt][0], c[nt][1]);
        uint32_t h1 = f2bf2(c[nt][2], c[nt][3]);
        float r0 = c[nt][0] - __uint_as_float(h0 << 16);
        float r1 = c[nt][1] - __uint_as_float(h0 & 0xffff0000u);
        float r2 = c[nt][2] - __uint_as_float(h1 << 16);
        float r3 = c[nt][3] - __uint_as_float(h1 & 0xffff0000u);
        qh[nt >> 1][(nt & 1) * 2 + 0] = h0;
        qh[nt >> 1][(nt & 1) * 2 + 1] = h1;
        ql[nt >> 1][(nt & 1) * 2 + 0] = f2bf2(r0, r1);
        ql[nt >> 1][(nt & 1) * 2 + 1] = f2bf2(r2, r3);
        int col = nt * 8 + qr * 2;
        *(uint32_t*)(g_qbf + hb + (size_t)(wr + grow) * HDIM + col) =
            f2bf2(c[nt][0] * ATT_SCALE, c[nt][1] * ATT_SCALE);
        *(uint32_t*)(g_qbf + hb + (size_t)(wr + grow + 8) * HDIM + col) =
            f2bf2(c[nt][2] * ATT_SCALE, c[nt][3] * ATT_SCALE);
    }

    // ---- k (pre-masked) ----
    proj_load_x(smc, xk, t);
    proj_load_w(smc, Wk, t);
    __syncthreads();
    #pragma unroll
    for (int i = 0; i < 8; i++)
        #pragma unroll
        for (int j = 0; j < 4; j++) c[i][j] = 0.0f;
    proj_mm(sb, wr, lane, c);
    __syncthreads();
    {
        const int* mrow = mask + n * SEQ + l0;
        const float mk0 = (float)mrow[wr + grow];
        const float mk1 = (float)mrow[wr + grow + 8];
        #pragma unroll
        for (int nt = 0; nt < 8; nt++) {
            int col = nt * 8 + qr * 2;
            *(uint32_t*)(g_kbf + hb + (size_t)(wr + grow) * HDIM + col) =
                f2bf2(c[nt][0] * mk0, c[nt][1] * mk0);
            *(uint32_t*)(g_kbf + hb + (size_t)(wr + grow + 8) * HDIM + col) =
                f2bf2(c[nt][2] * mk1, c[nt][3] * mk1);
        }
    }

    // ---- v = q Wv^T ----
    proj_load_w(smc, Wv, t);
    __syncthreads();
    #pragma unroll
    for (int i = 0; i < 8; i++)
        #pragma unroll
        for (int j = 0; j < 4; j++) c[i][j] = 0.0f;
    proj_mm_regA(sb, lane, qh, ql, c);
    #pragma unroll
    for (int nt = 0; nt < 8; nt++) {
        int col = nt * 8 + qr * 2;
        *(uint32_t*)(g_vbf + hb + (size_t)(wr + grow) * HDIM + col) = f2bf2(c[nt][0], c[nt][1]);
        *(uint32_t*)(g_vbf + hb + (size_t)(wr + grow + 8) * HDIM + col) = f2bf2(c[nt][2], c[nt][3]);
        *(float2*)(g_v + hb + (size_t)(wr + grow) * HDIM + col) = make_float2(c[nt][0], c[nt][1]);
        *(float2*)(g_v + hb + (size_t)(wr + grow + 8) * HDIM + col) = make_float2(c[nt][2], c[nt][3]);
    }
}

// ---------------------------------------------------------------------------
// Kernel 1b: masked V column sums + mask counts (once per (n,h))
// ---------------------------------------------------------------------------
__global__ __launch_bounds__(256) void colsum_kernel(const int* __restrict__ mask)
{
    const int bid = blockIdx.x, y = blockIdx.y;
    const float* V = g_v + (size_t)bid * SEQ * HDIM + (size_t)y * 512 * HDIM;
    const int* mg = mask + (bid >> 4) * SEQ + y * 512;
    const int d = threadIdx.x & 63, grp = threadIdx.x >> 6;
    float s = 0.0f;
    int scnt = 0;
    const float* vp = V + (size_t)grp * 128 * HDIM + d;
    const int* mp = mg + grp * 128;
    #pragma unroll 8
    for (int cc = 0; cc < 128; cc++) {
        int m = mp[cc];
        s = fmaf((float)m, vp[(size_t)cc * HDIM], s);
        scnt += m;
    }
    __shared__ float red[256];
    __shared__ int redc[4];
    red[threadIdx.x] = s;
    if (d == 0) redc[grp] = scnt;
    __syncthreads();
    if (threadIdx.x < 64)
        g_sv4[((size_t)bid * 4 + y) * HDIM + threadIdx.x] =
            red[threadIdx.x] + red[64 + threadIdx.x] + red[128 + threadIdx.x] + red[192 + threadIdx.x];
    if (threadIdx.x == 0)
        g_mcnt[bid * 4 + y] = (float)(redc[0] + redc[1] + redc[2] + redc[3]);
}

// ---------------------------------------------------------------------------
// Kernel 2: HMMA flash attention. Mask pre-baked into K (masked cols -> x=0
// -> delta=0), so the hot loop has NO mask handling at all.
// ---------------------------------------------------------------------------
#define A_QS 0
#define A_KS0 18432
#define A_KS1 36864
#define A_VS0 55296
#define A_VS1 73728
#define A_SVR 92160
#define A_CNT 92416
#define A_TOTAL 92432

__global__ __launch_bounds__(256, 2) void attn_hmma()
{
    extern __shared__ char smc[];
    const uint32_t sb = smem_u32(smc);
    const int t = threadIdx.x;
    const int w = t >> 5, lane = t & 31;
    const int grow = lane >> 2, qr = lane & 3;
    const int wr = w * 16;
    const int n = blockIdx.z, h = blockIdx.y, q0 = blockIdx.x * 128;
    const size_t hb = (size_t)(n * NHEAD + h) * SEQ;
    const __nv_bfloat16* Qg = g_qbf + (hb + q0) * HDIM;
    const __nv_bfloat16* Kg = g_kbf + hb * HDIM;
    const __nv_bfloat16* Vg = g_vbf + hb * HDIM;

    for (int i = t; i < 1024; i += 256) {
        int r = i >> 3, ch = i & 7;
        uint32_t so = (uint32_t)((r * SKW + ch * 8) * 2);
        cp16(sb + A_QS + so, Qg + r * 64 + ch * 8);
        cp16(sb + A_KS0 + so, Kg + r * 64 + ch * 8);
        cp16(sb + A_VS0 + so, Vg + r * 64 + ch * 8);
    }
    if (t < 64) {
        const float* s4 = g_sv4 + (size_t)(n * NHEAD + h) * 4 * HDIM;
        ((float*)(smc + A_SVR))[t] = s4[t] + s4[64 + t] + s4[128 + t] + s4[192 + t];
    }
    if (t < 4) ((float*)(smc + A_CNT))[t] = g_mcnt[(n * NHEAD + h) * 4 + t];
    CP_COMMIT();
    CP_WAIT(0);
    __syncthreads();

    uint32_t qf[4][4];
    {
        uint32_t qrow = (uint32_t)(wr + (lane & 7) + ((lane & 8) ? 8 : 0));
        uint32_t qcs = (lane & 16) ? 8u : 0u;
        #pragma unroll
        for (int kk = 0; kk < 4; kk++)
            ldm4(qf[kk][0], qf[kk][1], qf[kk][2], qf[kk][3],
                 sb + A_QS + (qrow * SKW + kk * 16 + qcs) * 2);
    }

    float of[9][4];
    #pragma unroll
    for (int i = 0; i < 9; i++)
        #pragma unroll
        for (int j = 0; j < 4; j++) of[i][j] = 0.0f;

    const uint32_t krow_b = (uint32_t)(lane & 7);
    const uint32_t ke = ((uint32_t)(lane >> 3)) * 8;
    const uint32_t vrow_b = (uint32_t)(((lane & 8) ? 8 : 0) + (lane & 7));
    const uint32_t vcs = (lane & 16) ? 8u : 0u;
    const uint32_t bones = (lane < 4) ? 0x3F803F80u : 0u;

    const __nv_bfloat162 C24 = __float2bfloat162_rn(4.1666667e-2f);
    const __nv_bfloat162 C6  = __float2bfloat162_rn(1.6666667e-1f);
    const __nv_bfloat162 C2  = __float2bfloat162_rn(0.5f);
    const __nv_bfloat162 C1  = __float2bfloat162_rn(1.0f);

    for (int tile = 0; tile < 16; tile++) {
        if (tile) __syncthreads();

        if (tile < 15) {
            const int kn = tile * 128 + 128;
            const __nv_bfloat16* ks = Kg + (size_t)kn * HDIM;
            const __nv_bfloat16* vs = Vg + (size_t)kn * HDIM;
            uint32_t kb = sb + ((tile + 1) & 1 ? A_KS1 : A_KS0);
            uint32_t vb = sb + ((tile + 1) & 1 ? A_VS1 : A_VS0);
            for (int i = t; i < 1024; i += 256) {
                int r = i >> 3, ch = i & 7;
                uint32_t so = (uint32_t)((r * SKW + ch * 8) * 2);
                cp16(kb + so, ks + r * 64 + ch * 8);
                cp16(vb + so, vs + r * 64 + ch * 8);
            }
            CP_COMMIT();
            CP_WAIT(1);
        } else {
            CP_WAIT(0);
        }
        __syncthreads();

        const uint32_t kb = sb + (tile & 1 ? A_KS1 : A_KS0);
        const uint32_t vb = sb + (tile & 1 ? A_VS1 : A_VS0);

        uint32_t pf[8][4];
        #pragma unroll
        for (int ct = 0; ct < 16; ct++) {
            float sa[4] = {0.0f, 0.0f, 0.0f, 0.0f};
            uint32_t base = kb + ((ct * 8 + krow_b) * SKW + ke) * 2;
            uint32_t b0, b1, b2, b3, b4, b5, b6, b7;
            ldm4(b0, b1, b2, b3, base);
            ldm4(b4, b5, b6, b7, base + 64);
            mma_bf16(sa, qf[0][0], qf[0][1], qf[0][2], qf[0][3], b0, b1);
            mma_bf16(sa, qf[1][0], qf[1][1], qf[1][2], qf[1][3], b2, b3);
            mma_bf16(sa, qf[2][0], qf[2][1], qf[2][2], qf[2][3], b4, b5);
            mma_bf16(sa, qf[3][0], qf[3][1], qf[3][2], qf[3][3], b6, b7);

            __nv_bfloat162 x01, x23;
            *(uint32_t*)&x01 = f2bf2(sa[0], sa[1]);
            *(uint32_t*)&x23 = f2bf2(sa[2], sa[3]);
            // delta = x*(1 + x*(1/2 + x*(1/6 + x/24))); masked cols have x==0 -> delta==0
            __nv_bfloat162 d01 = __hmul2(x01, __hfma2(x01, __hfma2(x01, __hfma2(x01, C24, C6), C2), C1));
            __nv_bfloat162 d23 = __hmul2(x23, __hfma2(x23, __hfma2(x23, __hfma2(x23, C24, C6), C2), C1));
            pf[ct >> 1][(ct & 1) * 2 + 0] = *(uint32_t*)&d01;
            pf[ct >> 1][(ct & 1) * 2 + 1] = *(uint32_t*)&d23;
        }

        #pragma unroll
        for (int kk = 0; kk < 8; kk++) {
            uint32_t rbase = vb + ((kk * 16 + vrow_b) * SKW + vcs) * 2;
            #pragma unroll
            for (int dg = 0; dg < 4; dg++) {
                uint32_t v0, v1, v2, v3;
                ldm4t(v0, v1, v2, v3, rbase + dg * 32);
                mma_bf16(of[2 * dg],     pf[kk][0], pf[kk][1], pf[kk][2], pf[kk][3], v0, v1);
                mma_bf16(of[2 * dg + 1], pf[kk][0], pf[kk][1], pf[kk][2], pf[kk][3], v2, v3);
            }
            mma_bf16(of[8], pf[kk][0], pf[kk][1], pf[kk][2], pf[kk][3], bones, bones);
        }
    }

    const float* c4 = (const float*)(smc + A_CNT);
    const float cnt = c4[0] + c4[1] + c4[2] + c4[3];
    float sd0 = __shfl_sync(0xffffffffu, of[8][0], lane & 28);
    float sd1 = __shfl_sync(0xffffffffu, of[8][2], lane & 28);
    const float inv0 = 1.0f / (cnt + sd0), inv1 = 1.0f / (cnt + sd1);

    const float* sv = (const float*)(smc + A_SVR);
    const size_t base0 = ((size_t)n * SEQ + q0 + wr + grow) * EMBD + h * HDIM;
    const size_t base1 = base0 + (size_t)8 * EMBD;
    #pragma unroll
    for (int dt = 0; dt < 8; dt++) {
        int j0 = dt * 8 + qr * 2;
        float o00 = (of[dt][0] + sv[j0]) * inv0;
        float o01 = (of[dt][1] + sv[j0 + 1]) * inv0;
        float o10 = (of[dt][2] + sv[j0]) * inv1;
        float o11 = (of[dt][3] + sv[j0 + 1]) * inv1;
        uint32_t h0 = f2bf2(o00, o01);
        uint32_t h1 = f2bf2(o10, o11);
        float r00 = o00 - __uint_as_float(h0 << 16);
        float r01 = o01 - __uint_as_float(h0 & 0xffff0000u);
        float r10 = o10 - __uint_as_float(h1 << 16);
        float r11 = o11 - __uint_as_float(h1 & 0xffff0000u);
        *(uint32_t*)(g_ahi + base0 + j0) = h0;
        *(uint32_t*)(g_ahi + base1 + j0) = h1;
        *(uint32_t*)(g_alo + base0 + j0) = f2bf2(r00, r01);
        *(uint32_t*)(g_alo + base1 + j0) = f2bf2(r10, r11);
    }
}

// ---------------------------------------------------------------------------
// Kernel 3a: Wo -> hi/lo bf16 split
// ---------------------------------------------------------------------------
__global__ __launch_bounds__(256) void wo_prep(const float* __restrict__ Wo)
{
    int i = blockIdx.x * 256 + threadIdx.x;
    float wv = Wo[i];
    __nv_bfloat16 hi = __float2bfloat16(wv);
    g_whi[i] = hi;
    g_wlo[i] = __float2bfloat16(wv - __bfloat162float(hi));
}

// ---------------------------------------------------------------------------
// Kernel 3b: out = attn @ Wo^T + bo (HMMA 3-way split, cp.async double buffer)
// [REVERTED to the R5/R7 measured-74.5us version]
// ---------------------------------------------------------------------------
#define O_STAGE 73728
#define O_AH 0
#define O_AL 18432
#define O_WH 36864
#define O_WL 55296
#define O_TOTAL (2 * O_STAGE)

__global__ __launch_bounds__(256, 1) void out_hmma(const float* __restrict__ bo, float* __restrict__ out)
{
    extern __shared__ char smc[];
    const uint32_t sb = smem_u32(smc);
    const int t = threadIdx.x;
    const int w = t >> 5, lane = t & 31;
    const int grow = lane >> 2, qr = lane & 3;
    const int o0 = blockIdx.x * 128, m0 = blockIdx.y * 128;
    const int my = (w >> 2) * 64, ox = (w & 3) * 32;

    const __nv_bfloat16* AHg = g_ahi + (size_t)m0 * EMBD;
    const __nv_bfloat16* ALg = g_alo + (size_t)m0 * EMBD;
    const __nv_bfloat16* WHg = g_whi + (size_t)o0 * EMBD;
    const __nv_bfloat16* WLg = g_wlo + (size_t)o0 * EMBD;

    for (int i = t; i < 1024; i += 256) {
        int r = i >> 3, ch = i & 7;
        uint32_t so = (uint32_t)((r * SKW + ch * 8) * 2);
        size_t go = (size_t)r * EMBD + ch * 8;
        cp16(sb + O_AH + so, AHg + go);
        cp16(sb + O_AL + so, ALg + go);
        cp16(sb + O_WH + so, WHg + go);
        cp16(sb + O_WL + so, WLg + go);
    }
    CP_COMMIT();

    float cf[4][4][4];
    #pragma unroll
    for (int i = 0; i < 4; i++)
        #pragma unroll
        for (int j = 0; j < 4; j++)
            #pragma unroll
            for (int k = 0; k < 4; k++) cf[i][j][k] = 0.0f;

    const uint32_t arow = (uint32_t)(my + (lane & 7) + ((lane & 8) ? 8 : 0));
    const uint32_t acs = (lane & 16) ? 8u : 0u;
    const uint32_t brow = (uint32_t)(ox + ((lane & 16) ? 8 : 0) + (lane & 7));
    const uint32_t bcs = (lane & 8) ? 8u : 0u;

    for (int ec = 0; ec < 16; ec++) {
        if (ec) __syncthreads();

        if (ec < 15) {
            uint32_t stage = sb + ((ec + 1) & 1) * O_STAGE;
            size_t gb = (size_t)(ec + 1) * 64;
            for (int i = t; i < 1024; i += 256) {
                int r = i >> 3, ch = i & 7;
                uint32_t so = (uint32_t)((r * SKW + ch * 8) * 2);
                size_t go = (size_t)r * EMBD + gb + ch * 8;
                cp16(stage + O_AH + so, AHg + go);
                cp16(stage + O_AL + so, ALg + go);
                cp16(stage + O_WH + so, WHg + go);
                cp16(stage + O_WL + so, WLg + go);
            }
            CP_COMMIT();
            CP_WAIT(1);
        } else {
            CP_WAIT(0);
        }
        __syncthreads();

        const uint32_t st = sb + (ec & 1) * O_STAGE;
        #pragma unroll
        for (int kk = 0; kk < 4; kk++) {
            uint32_t ah[4][4], al[4][4], bh[4][2], bl[4][2];
            #pragma unroll
            for (int mt = 0; mt < 4; mt++) {
                uint32_t off = (((arow + mt * 16) * SKW) + kk * 16 + acs) * 2;
                ldm4(ah[mt][0], ah[mt][1], ah[mt][2], ah[mt][3], st + O_AH + off);
                ldm4(al[mt][0], al[mt][1], al[mt][2], al[mt][3], st + O_AL + off);
            }
            #pragma unroll
            for (int p = 0; p < 2; p++) {
                uint32_t off = (((brow + p * 16) * SKW) + kk * 16 + bcs) * 2;
                ldm4(bh[2 * p][0], bh[2 * p][1], bh[2 * p + 1][0], bh[2 * p + 1][1], st + O_WH + off);
                ldm4(bl[2 * p][0], bl[2 * p][1], bl[2 * p + 1][0], bl[2 * p + 1][1], st + O_WL + off);
            }
            #pragma unroll
            for (int mt = 0; mt < 4; mt++)
                #pragma unroll
                for (int nt = 0; nt < 4; nt++) {
                    mma_bf16(cf[mt][nt], ah[mt][0], ah[mt][1], ah[mt][2], ah[mt][3], bh[nt][0], bh[nt][1]);
                    mma_bf16(cf[mt][nt], ah[mt][0], ah[mt][1], ah[mt][2], ah[mt][3], bl[nt][0], bl[nt][1]);
                    mma_bf16(cf[mt][nt], al[mt][0], al[mt][1], al[mt][2], al[mt][3], bh[nt][0], bh[nt][1]);
                }
        }
    }

    #pragma unroll
    for (int mt = 0; mt < 4; mt++) {
        int row = m0 + my + mt * 16 + grow;
        #pragma unroll
        for (int nt = 0; nt < 4; nt++) {
            int col = o0 + ox + nt * 8 + qr * 2;
            float b0 = bo[col], b1 = bo[col + 1];
            *(float2*)(out + (size_t)row * EMBD + col) =
                make_float2(cf[mt][nt][0] + b0, cf[mt][nt][1] + b1);
            *(float2*)(out + (size_t)(row + 8) * EMBD + col) =
                make_float2(cf[mt][nt][2] + b0, cf[mt][nt][3] + b1);
        }
    }
}

// ---------------------------------------------------------------------------
extern "C" void kernel_launch(void* const* d_in, const int* in_sizes, int n_in,
                              void* d_out, int out_size)
{
    const float* keys    = (const float*)d_in[0];
    const float* queries = (const float*)d_in[1];
    const int*   mask    = (const int*)d_in[3];
    const float* Wk      = (const float*)d_in[4];
    const float* Wq      = (const float*)d_in[5];
    const float* Wv      = (const float*)d_in[6];
    const float* Wo      = (const float*)d_in[7];
    const float* bo      = (const float*)d_in[8];
    float* out = (float*)d_out;

    cudaFuncSetAttribute(proj_hmma, cudaFuncAttributeMaxDynamicSharedMemorySize, P_TOTAL);
    cudaFuncSetAttribute(attn_hmma, cudaFuncAttributeMaxDynamicSharedMemorySize, A_TOTAL);
    cudaFuncSetAttribute(out_hmma, cudaFuncAttributeMaxDynamicSharedMemorySize, O_TOTAL);

    dim3 gp(SEQ / 128, NHEAD, NBATCH);
    proj_hmma<<<gp, 256, P_TOTAL>>>(keys, queries, Wk, Wq, Wv, mask);
    dim3 gc(NBATCH * NHEAD, 4);
    colsum_kernel<<<gc, 256>>>(mask);
    wo_prep<<<(EMBD * EMBD) / 256, 256>>>(Wo);
    dim3 ga(SEQ / 128, NHEAD, NBATCH);
    attn_hmma<<<ga, 256, A_TOTAL>>>();
    dim3 go(EMBD / 128, NBATCH * SEQ / 128);
    out_hmma<<<go, 256, O_TOTAL>>>(bo, out);
}